// round 17
// baseline (speedup 1.0000x reference)
#include <cuda_runtime.h>
#include <cuda_fp16.h>
#include <cstdint>

// ---------------------------------------------------------------------------
// 4D ConvTranspose stride2 K=3^4, parity classes paired along dim4 (R15).
// R17: each CTA = TWO independent 128-thread half-pipelines (named barriers,
// own 3-stage cp.async ring, own B copy). 4 independent pipelines/SM kill
// the per-tap barrier convoy that bound R12-R16 (tap wall 3850cyc vs ~1200
// issueable). Tensor: ldmatrix + mma.sync m16n8k16 f16 fp32-acc (2.9e-4).
// ---------------------------------------------------------------------------

#define XM 20736            // 12^4 input spatial points
#define OSB 25000000LL
#define OSC 390625
#define OS1 15625
#define OS2 625
#define OS3 25

// prepped operands
__device__ __align__(16) __half g_w16[81*64*64];   // [kidx][co][ci]
__device__ __align__(16) __half g_x16[4L*XM*64];   // [b][m_lin][ci]

// dynamic SMEM: per half: 3-stage ring of (A 64x128B, B 64x128B).
#define SM_A    0            // 2 halves x 3 x 8192 = 49152
#define SM_B    49152        // 2 halves x 3 x 8192 = 49152
#define SM_OFFS 98304        // u16[24*128] = 6144
#define SM_BIAS 104448       // float[64]
#define SM_KOF  104704       // int[24]
#define SM_DD   104800       // char[24][4]
#define SM_TOTAL 104960

#define SWZ(o) ((o) ^ (((o) >> 3) & 0x70))

// ---------------- fused prep kernel ----------------
__global__ void prep_all(const float* __restrict__ w, const float* __restrict__ x) {
    if (blockIdx.x < 1296) {
        int idx = blockIdx.x * 256 + threadIdx.x;
        if (idx >= 331776) return;                 // 64*64*81
        int ci = idx / 5184;
        int r  = idx - ci * 5184;
        int co = r / 81;
        int k  = r - co * 81;
        g_w16[(k * 64 + co) * 64 + ci] = __float2half(w[idx]);
    } else {
        __shared__ float s[64][33];
        int q = blockIdx.x - 1296;                 // 0..2591
        int b = q / 648, m0 = (q - b * 648) * 32, tid = threadIdx.x;
        for (int i = tid; i < 2048; i += 256) {
            int ci = i >> 5, mm = i & 31;
            s[ci][mm] = x[((size_t)(b * 64 + ci)) * XM + m0 + mm];
        }
        __syncthreads();
        int m = tid >> 3, qq = tid & 7;
        union { __half a[8]; uint4 v; } hv;
        #pragma unroll
        for (int j = 0; j < 8; j++)
            hv.a[j] = __float2half(s[qq * 8 + j][m]);
        *(uint4*)(g_x16 + ((size_t)b * XM + m0 + m) * 64 + qq * 8) = hv.v;
    }
}

// ---------------- ptx helpers ----------------
__device__ __forceinline__ uint32_t smem_u32(const void* p) {
    uint32_t a;
    asm("{ .reg .u64 t; cvta.to.shared.u64 t, %1; cvt.u32.u64 %0, t; }" : "=r"(a) : "l"(p));
    return a;
}
__device__ __forceinline__ void ldsm4(uint32_t r[4], uint32_t addr) {
    asm volatile("ldmatrix.sync.aligned.m8n8.x4.shared.b16 {%0,%1,%2,%3}, [%4];"
                 : "=r"(r[0]), "=r"(r[1]), "=r"(r[2]), "=r"(r[3]) : "r"(addr));
}
__device__ __forceinline__ void mma_f16(float c[4], const uint32_t a[4],
                                        uint32_t b0, uint32_t b1) {
    asm volatile("mma.sync.aligned.m16n8k16.row.col.f32.f16.f16.f32 "
                 "{%0,%1,%2,%3}, {%4,%5,%6,%7}, {%8,%9}, {%0,%1,%2,%3};"
                 : "+f"(c[0]), "+f"(c[1]), "+f"(c[2]), "+f"(c[3])
                 : "r"(a[0]), "r"(a[1]), "r"(a[2]), "r"(a[3]), "r"(b0), "r"(b1));
}
__device__ __forceinline__ void cpa16(uint32_t dst, const void* src, bool pred) {
    int sz = pred ? 16 : 0;
    asm volatile("cp.async.cg.shared.global [%0], [%1], 16, %2;"
                 :: "r"(dst), "l"(src), "r"(sz) : "memory");
}
__device__ __forceinline__ void commit_group() {
    asm volatile("cp.async.commit_group;" ::: "memory");
}
__device__ __forceinline__ void barx(int id) {
    asm volatile("bar.sync %0, 128;" :: "r"(id) : "memory");
}

// unrolled mma body on accumulator bank AC
#define MMA_TAP(AC)                                                            \
    {                                                                          \
        _Pragma("unroll")                                                      \
        for (int kk = 0; kk < 4; kk++) {                                       \
            uint32_t Af[2][4];                                                 \
            const uint32_t acol = kk * 32 + aseg;                              \
            _Pragma("unroll")                                                  \
            for (int i = 0; i < 2; i++)                                        \
                ldsm4(Af[i], abase + SWZ((ws * 32 + i * 16 + arow_s) * 128 + acol)); \
            _Pragma("unroll")                                                  \
            for (int jp = 0; jp < 2; jp++) {                                   \
                uint32_t Bf[4];                                                \
                ldsm4(Bf, bbase + SWZ((wc * 32 + jp * 16 + brow_s) * 128 + kk * 32 + bseg)); \
                _Pragma("unroll")                                              \
                for (int i = 0; i < 2; i++) {                                  \
                    mma_f16(AC[i][2 * jp],     Af[i], Bf[0], Bf[1]);           \
                    mma_f16(AC[i][2 * jp + 1], Af[i], Bf[2], Bf[3]);           \
                }                                                              \
            }                                                                  \
        }                                                                      \
    }

// ---------------- main kernel ----------------
__global__ __launch_bounds__(256, 2) void ct4d_mma(
    const float* __restrict__ bias, float* __restrict__ out)
{
    extern __shared__ char smem[];
    const int tid = threadIdx.x, lane = tid & 31, wrp = tid >> 5;
    const int hh = wrp >> 2;          // half 0/1 (sp rows hh*64 .. +63)
    const int ws = (wrp >> 1) & 1;    // sp block within half (32 rows)
    const int wc = wrp & 1;           // co block (32 cols)
    const int tid_h = tid & 127;      // thread id within half
    const int c = blockIdx.z, b = blockIdx.y, tile = blockIdx.x;
    const int p1 = (c >> 2) & 1, p2 = (c >> 1) & 1, p3 = c & 1;
    const int n1 = 13 - p1, n2 = 13 - p2, n3 = 13 - p3;
    const int Ntot = n1 * n2 * n3 * 13;      // m4 grid is class-0's (13)
    if (tile * 128 >= Ntot) return;
    const int T123 = 1 << (3 - p1 - p2 - p3);
    const int NT = 3 * T123;                 // >= 3 always

    const uint32_t sb = smem_u32(smem);
    int*          kof  = (int*)(smem + SM_KOF);
    signed char (*dd)[4] = (signed char(*)[4])(smem + SM_DD);
    uint16_t*     offs = (uint16_t*)(smem + SM_OFFS);
    float*        bs   = (float*)(smem + SM_BIAS);

    if (tid < NT) {
        int t123 = tid / 3, j = tid - (tid / 3) * 3;
        int rem = t123, pp[3] = {p1, p2, p3}, d[3], k[3];
        #pragma unroll
        for (int i = 0; i < 3; i++) {
            if (!pp[i]) { d[i] = rem & 1; rem >>= 1; k[i] = 2 * d[i]; }
            else        { d[i] = 0;                  k[i] = 1; }
        }
        int k4 = (j < 2) ? 2 * j : 1;
        int d4 = (j < 2) ? j : 0;
        kof[tid] = ((k[0] * 3 + k[1]) * 3 + k[2]) * 3 + k4;
        dd[tid][0] = d[0]; dd[tid][1] = d[1]; dd[tid][2] = d[2]; dd[tid][3] = d4;
    }
    if (tid < 64) bs[tid] = bias[tid];
    __syncthreads();

    // gather offsets per (tap, sp row); 0xFFFF = OOB/pad
    if (tid < 128) {
        int g = tile * 128 + tid;
        int valid = g < Ntot, m1 = 0, m2 = 0, m3 = 0, m4 = 0;
        if (valid) { m4 = g % 13; int q = g / 13; m3 = q % n3; q /= n3; m2 = q % n2; m1 = q / n2; }
        for (int t = 0; t < NT; t++) {
            int off = 0xFFFF;
            if (valid) {
                int a1 = m1 - dd[t][0], a2 = m2 - dd[t][1], a3 = m3 - dd[t][2], a4 = m4 - dd[t][3];
                if (((unsigned)a1 < 12u) & ((unsigned)a2 < 12u) & ((unsigned)a3 < 12u) & ((unsigned)a4 < 12u))
                    off = ((a1 * 12 + a2) * 12 + a3) * 12 + a4;
            }
            offs[t * 128 + tid] = (uint16_t)off;
        }
    }
    __syncthreads();   // offs + tables visible; NO CTA-wide syncs after this

    const __half* xb = g_x16 + (size_t)b * XM * 64;
    const uint32_t aring = sb + SM_A + hh * 24576;   // this half's rings
    const uint32_t bring = sb + SM_B + hh * 24576;

    // stage one tap into this HALF's ring slot bf (own B copy). 128 threads.
    auto stage = [&](int t, int bf) {
        // B: 64 rows x 128B: 2 threads/row x 4 segs each.
        {
            const int kb = kof[t] * 64;
            int r = tid_h >> 1, sbase = (tid_h & 1) * 4;
            #pragma unroll
            for (int s = 0; s < 4; s++) {
                int seg = sbase + s;
                cpa16(bring + bf * 8192 + SWZ(r * 128 + seg * 16),
                      g_w16 + (kb + r) * 64 + seg * 8, true);
            }
        }
        // A: this half's 64 sp rows (8 threads/row, 16 rows/pass, 4 passes)
        {
            const uint16_t* ot = offs + t * 128 + hh * 64;
            int q8 = tid_h & 7, rsub = tid_h >> 3;
            #pragma unroll
            for (int rb = 0; rb < 64; rb += 16) {
                int r = rb + rsub;
                uint32_t off = ot[r];
                bool ok = off != 0xFFFFu;
                cpa16(aring + bf * 8192 + SWZ(r * 128 + q8 * 16),
                      xb + (size_t)(ok ? off : 0) * 64 + q8 * 8, ok);
            }
        }
        commit_group();
    };

    float acc0[2][4][4], acc1[2][4][4];
    #pragma unroll
    for (int i = 0; i < 2; i++)
        #pragma unroll
        for (int j = 0; j < 4; j++)
            #pragma unroll
            for (int q = 0; q < 4; q++) { acc0[i][j][q] = 0.f; acc1[i][j][q] = 0.f; }

    stage(0, 0);
    stage(1, 1);

    const int arow_s = lane & 15;
    const int aseg   = ((lane >> 4) & 1) * 16;
    const int brow_s = ((lane >> 4) & 1) * 8 + (lane & 7);
    const int bseg   = ((lane >> 3) & 1) * 16;

    for (int t = 0; t < NT; t++) {
        const int bf = t % 3;
        // group t committed 2 taps ago; allow 1 newer outstanding.
        asm volatile("cp.async.wait_group 1;" ::: "memory");
        barx(1 + hh);   // half-wide: stage(t) visible + compute(t-1) done
        if (t + 2 < NT) stage(t + 2, (t + 2) % 3); else commit_group();

        const uint32_t abase = aring + bf * 8192;
        const uint32_t bbase = bring + bf * 8192;

        if (t - (t / 3) * 3 == 2) {   // k4=1 tap -> odd-parity accumulator
            MMA_TAP(acc1)
        } else {                       // k4 in {0,2} -> even-parity accumulator
            MMA_TAP(acc0)
        }
    }

    // epilogue: both parities per point -> adjacent floats -> full sectors
    float* ob = out + (size_t)b * OSB;
    const int gbase = tile * 128 + hh * 64 + ws * 32 + (lane >> 2);
    #pragma unroll
    for (int i = 0; i < 2; i++) {
        #pragma unroll
        for (int h = 0; h < 2; h++) {
            int g = gbase + i * 16 + h * 8;
            if (g >= Ntot) continue;
            int m4 = g % 13; int q = g / 13;
            int m3 = q % n3; q /= n3;
            int m2 = q % n2; int m1 = q / n2;
            long o = (long)(2 * m1 + p1) * OS1 + (2 * m2 + p2) * OS2 +
                     (2 * m3 + p3) * OS3 + 2 * m4;
            float* op = ob + o;
            bool odd_ok = m4 < 12;     // class-1 grid is 12 along m4
            #pragma unroll
            for (int j = 0; j < 4; j++) {
                int co = wc * 32 + j * 8 + (lane & 3) * 2;
                float b0 = bs[co], b1 = bs[co + 1];
                op[(size_t)co * OSC]           = acc0[i][j][2 * h]     + b0;
                op[(size_t)(co + 1) * OSC]     = acc0[i][j][2 * h + 1] + b1;
                if (odd_ok) {
                    op[(size_t)co * OSC + 1]       = acc1[i][j][2 * h]     + b0;
                    op[(size_t)(co + 1) * OSC + 1] = acc1[i][j][2 * h + 1] + b1;
                }
            }
        }
    }
}

extern "C" void kernel_launch(void* const* d_in, const int* in_sizes, int n_in,
                              void* d_out, int out_size) {
    const float* x    = (const float*)d_in[0];
    const float* w    = (const float*)d_in[1];
    const float* bias = (const float*)d_in[2];
    float* out = (float*)d_out;

    cudaFuncSetAttribute(ct4d_mma, cudaFuncAttributeMaxDynamicSharedMemorySize, SM_TOTAL);

    prep_all<<<3888, 256>>>(w, x);
    // 224 = ceil(13^3*13 / 128); z = 8 paired classes (p1,p2,p3).
    ct4d_mma<<<dim3(224, 4, 8), 256, SM_TOTAL>>>(bias, out);
}